// round 10
// baseline (speedup 1.0000x reference)
#include <cuda_runtime.h>
#include <cuda_bf16.h>
#include <cstdint>

// Embedding gather: out[t, :] = W_E[tokens[t], :]
// tokens: int32 [32768], W_E: float32 [50257, 768], out: float32 [32768, 768]
//
// R9 -> R10 (consolidation): five orthogonal mechanisms (reg-MLP, bulk engine,
// cp.async deep pipeline, L2 policy, 256-bit requests) all plateau at
// ~4.6-4.9 TB/s on the ~125MB mixed read/write stream -> that IS the DRAM
// ceiling for this pattern. This round stacks the best pieces:
//   - 256-bit accesses (LDG.256 evict_last / STG.256 .cs), 1KB/warp bursts
//   - __launch_bounds__(192, 6): 56-reg budget so the 8-deep load batch is
//     genuinely live (R9 got squeezed to 32 regs)
//   - 16 rows per 192-thread CTA, thread owns 32B of each row

#define ROW_BYTES 3072
#define TPR       96        // threads per row (32B each)
#define U         8         // row-pairs per CTA -> 16 rows
#define ROWS_PER_CTA (2 * U)

__global__ __launch_bounds__(192, 6) void embed_gather_v8_kernel(
    const int* __restrict__ tokens,
    const unsigned char* __restrict__ W,
    unsigned char* __restrict__ out,
    int n_tok)
{
    const int t    = threadIdx.x;
    const int half = t / TPR;             // 0 or 1
    const int boff = (t % TPR) * 32;      // byte offset within a row
    const int t0   = blockIdx.x * ROWS_PER_CTA;

    if (t0 + ROWS_PER_CTA <= n_tok) {
        int rows[U];
#pragma unroll
        for (int s = 0; s < U; ++s)
            rows[s] = __ldg(tokens + t0 + 2 * s + half);

        uint32_t v[U][8];
#pragma unroll
        for (int s = 0; s < U; ++s) {
            const unsigned char* src = W + (size_t)rows[s] * ROW_BYTES + boff;
            asm volatile(
                "ld.global.nc.L2::evict_last.v8.b32 "
                "{%0, %1, %2, %3, %4, %5, %6, %7}, [%8];"
                : "=r"(v[s][0]), "=r"(v[s][1]), "=r"(v[s][2]), "=r"(v[s][3]),
                  "=r"(v[s][4]), "=r"(v[s][5]), "=r"(v[s][6]), "=r"(v[s][7])
                : "l"(src));
        }

#pragma unroll
        for (int s = 0; s < U; ++s) {
            unsigned char* dst =
                out + (size_t)(t0 + 2 * s + half) * ROW_BYTES + boff;
            asm volatile(
                "st.global.cs.v8.b32 [%0], "
                "{%1, %2, %3, %4, %5, %6, %7, %8};"
                :: "l"(dst),
                   "r"(v[s][0]), "r"(v[s][1]), "r"(v[s][2]), "r"(v[s][3]),
                   "r"(v[s][4]), "r"(v[s][5]), "r"(v[s][6]), "r"(v[s][7])
                : "memory");
        }
    } else {
        // tail: 32B-per-thread copy, one row at a time
        for (int r = t0 + half; r < n_tok; r += 2) {
            const int row = __ldg(tokens + r);
            uint32_t w[8];
            const unsigned char* src = W + (size_t)row * ROW_BYTES + boff;
            asm volatile(
                "ld.global.nc.v8.b32 {%0, %1, %2, %3, %4, %5, %6, %7}, [%8];"
                : "=r"(w[0]), "=r"(w[1]), "=r"(w[2]), "=r"(w[3]),
                  "=r"(w[4]), "=r"(w[5]), "=r"(w[6]), "=r"(w[7])
                : "l"(src));
            unsigned char* dst = out + (size_t)r * ROW_BYTES + boff;
            asm volatile(
                "st.global.cs.v8.b32 [%0], {%1, %2, %3, %4, %5, %6, %7, %8};"
                :: "l"(dst),
                   "r"(w[0]), "r"(w[1]), "r"(w[2]), "r"(w[3]),
                   "r"(w[4]), "r"(w[5]), "r"(w[6]), "r"(w[7])
                : "memory");
        }
    }
}

extern "C" void kernel_launch(void* const* d_in, const int* in_sizes, int n_in,
                              void* d_out, int out_size)
{
    const int* tokens      = (const int*)d_in[0];
    const unsigned char* W = (const unsigned char*)d_in[1];
    unsigned char* out     = (unsigned char*)d_out;

    const int n_tok = in_sizes[0];   // 32768
    const int grid  = (n_tok + ROWS_PER_CTA - 1) / ROWS_PER_CTA;  // 2048

    embed_gather_v8_kernel<<<grid, 192>>>(tokens, W, out, n_tok);
}

// round 11
// speedup vs baseline: 1.0077x; 1.0077x over previous
#include <cuda_runtime.h>
#include <cuda_bf16.h>

// Embedding gather: out[t, :] = W_E[tokens[t], :]
// tokens: int32 [32768]   (d_in[0])
// W_E:    float32 [50257, 768]  (d_in[1])
// out:    float32 [32768, 768]
//
// FINAL (R11): the full mechanism matrix (register MLP, cp.async.bulk one-shot
// and persistent-pipelined, cp.async 4-stage ring, L2 evict_last/evict_first
// policies, 256-bit LDG/STG) converges to ~123-127 MB of mixed random-read +
// streaming-write DRAM traffic at a hard ~4.7-4.9 TB/s ceiling — the roofline
// for this pattern. This is the fastest measured variant (25.79 us kernel):
// 8 tokens per 192-thread CTA, batched 8x independent 128B-per-warp row loads
// (MLP=8) then 8 coalesced float4 stores. Simple codegen, 32 regs, occ ~76%.

#define D_MODEL 768
#define V4 (D_MODEL / 4)   // 192 float4 per row
#define U 8                // tokens per CTA

__global__ __launch_bounds__(V4) void embed_gather_kernel(
    const int* __restrict__ tokens,
    const float4* __restrict__ W,
    float4* __restrict__ out,
    int n_tok)
{
    const int col = threadIdx.x;
    const int t0  = blockIdx.x * U;

    if (t0 + U <= n_tok) {
        // fast path: full group of U tokens
        int rows[U];
#pragma unroll
        for (int u = 0; u < U; ++u)
            rows[u] = __ldg(tokens + t0 + u);       // independent, L2-hot

        float4 v[U];
#pragma unroll
        for (int u = 0; u < U; ++u)
            v[u] = __ldg(W + (size_t)rows[u] * V4 + col);   // 8 independent 128B/warp loads

#pragma unroll
        for (int u = 0; u < U; ++u)
            out[(size_t)(t0 + u) * V4 + col] = v[u];
    } else {
        for (int t = t0; t < n_tok; ++t) {
            int row = __ldg(tokens + t);
            out[(size_t)t * V4 + col] = __ldg(W + (size_t)row * V4 + col);
        }
    }
}

extern "C" void kernel_launch(void* const* d_in, const int* in_sizes, int n_in,
                              void* d_out, int out_size)
{
    const int* tokens = (const int*)d_in[0];
    const float4* W   = (const float4*)d_in[1];
    float4* out       = (float4*)d_out;

    const int n_tok = in_sizes[0];   // 32768
    const int grid  = (n_tok + U - 1) / U;

    embed_gather_kernel<<<grid, V4>>>(tokens, W, out, n_tok);
}

// round 12
// speedup vs baseline: 1.0738x; 1.0656x over previous
#include <cuda_runtime.h>
#include <cuda_bf16.h>

// Embedding gather: out[t, :] = W_E[tokens[t], :]
// tokens: int32 [32768]   (d_in[0])
// W_E:    float32 [50257, 768]  (d_in[1])
// out:    float32 [32768, 768]
//
// R11 -> R12 (last matrix cell): R2/R11 structure is the fastest measured
// (25.5us kernel, 4.95 TB/s). Only untested combo: plain __ldg reads + pure
// st.global.cs (evict-first) writes, with NO read-policy operand (R8's
// createpolicy added a 64-bit operand per load and was slower). Theory: the
// 96MB write stream churns W_E (74MB unique) out of the 126MB L2; evict-first
// writes preserve read residency and cut the ~27MB read-miss component.

#define D_MODEL 768
#define V4 (D_MODEL / 4)   // 192 float4 per row
#define U 8                // tokens per CTA

__global__ __launch_bounds__(V4) void embed_gather_kernel(
    const int* __restrict__ tokens,
    const float4* __restrict__ W,
    float4* __restrict__ out,
    int n_tok)
{
    const int col = threadIdx.x;
    const int t0  = blockIdx.x * U;

    if (t0 + U <= n_tok) {
        int rows[U];
#pragma unroll
        for (int u = 0; u < U; ++u)
            rows[u] = __ldg(tokens + t0 + u);       // independent, L2-hot

        float4 v[U];
#pragma unroll
        for (int u = 0; u < U; ++u)
            v[u] = __ldg(W + (size_t)rows[u] * V4 + col);   // 8 independent 128B/warp loads

#pragma unroll
        for (int u = 0; u < U; ++u) {
            float4* dst = out + (size_t)(t0 + u) * V4 + col;
            asm volatile(
                "st.global.cs.v4.f32 [%0], {%1, %2, %3, %4};"
                :: "l"(dst), "f"(v[u].x), "f"(v[u].y), "f"(v[u].z), "f"(v[u].w)
                : "memory");
        }
    } else {
        for (int t = t0; t < n_tok; ++t) {
            int row = __ldg(tokens + t);
            float4 v = __ldg(W + (size_t)row * V4 + col);
            float4* dst = out + (size_t)t * V4 + col;
            asm volatile(
                "st.global.cs.v4.f32 [%0], {%1, %2, %3, %4};"
                :: "l"(dst), "f"(v.x), "f"(v.y), "f"(v.z), "f"(v.w)
                : "memory");
        }
    }
}

extern "C" void kernel_launch(void* const* d_in, const int* in_sizes, int n_in,
                              void* d_out, int out_size)
{
    const int* tokens = (const int*)d_in[0];
    const float4* W   = (const float4*)d_in[1];
    float4* out       = (float4*)d_out;

    const int n_tok = in_sizes[0];   // 32768
    const int grid  = (n_tok + U - 1) / U;

    embed_gather_kernel<<<grid, V4>>>(tokens, W, out, n_tok);
}